// round 6
// baseline (speedup 1.0000x reference)
#include <cuda_runtime.h>
#include <cuda_bf16.h>
#include <cstdint>

#define MAX_I   100000
#define MAX_B   16384
#define NUM_SEG (MAX_B * 5)

__device__ float g_rowsum[MAX_I];
__device__ float g_segsum[NUM_SEG];
__device__ float g_segcnt[NUM_SEG];
__device__ float g_dot[MAX_B];
__device__ float g_isum[MAX_B];

// ---------------------------------------------------------------------------
// mbarrier / bulk-copy helpers
// ---------------------------------------------------------------------------
__device__ __forceinline__ uint32_t smem_u32(const void* p) {
    uint32_t a;
    asm("{ .reg .u64 t; cvta.to.shared.u64 t, %1; cvt.u32.u64 %0, t; }"
        : "=r"(a) : "l"(p));
    return a;
}

#define MBAR_INIT(mbar, cnt) \
    asm volatile("mbarrier.init.shared.b64 [%0], %1;" :: "r"(mbar), "r"(cnt) : "memory")

#define MBAR_EXPECT_TX(mbar, bytes) \
    asm volatile("mbarrier.arrive.expect_tx.shared.b64 _, [%0], %1;" \
                 :: "r"(mbar), "r"(bytes) : "memory")

#define CP_ASYNC_BULK(dst_smem, src_gmem, bytes, mbar) \
    asm volatile("cp.async.bulk.shared::cluster.global.mbarrier::complete_tx::bytes " \
                 "[%0], [%1], %2, [%3];" \
                 :: "r"(dst_smem), "l"(src_gmem), "r"(bytes), "r"(mbar) : "memory")

__device__ __forceinline__ void mbar_wait(uint32_t mbar, uint32_t parity) {
    uint32_t done;
    asm volatile(
        "{\n\t.reg .pred p;\n\t"
        "mbarrier.try_wait.parity.acquire.cta.shared::cta.b64 p, [%1], %2;\n\t"
        "selp.b32 %0, 1, 0, p;\n\t}"
        : "=r"(done) : "r"(mbar), "r"(parity) : "memory");
    if (!done) {
        asm volatile(
            "{\n\t.reg .pred P1;\n\t"
            "WL_%=:\n\t"
            "mbarrier.try_wait.parity.acquire.cta.shared::cta.b64 P1, [%0], %1, 0x989680;\n\t"
            "@P1 bra.uni WD_%=;\n\t"
            "bra.uni WL_%=;\n\t"
            "WD_%=:\n\t}"
            :: "r"(mbar), "r"(parity) : "memory");
    }
}

// ---------------------------------------------------------------------------
// Kernel 1: zero accumulators + rowsum via cp.async.bulk pipeline.
// 148 persistent blocks x 256 threads. Tile = 64 rows (16KB), 4 stages.
// ---------------------------------------------------------------------------
#define K1_BLK   148
#define K1_THR   256
#define NSTAGE   4
#define TILE_ROWS 64
#define TILE_BYTES (TILE_ROWS * 256)
#define K1_SMEM  (NSTAGE * TILE_BYTES + NSTAGE * 8 + 64)

__global__ void __launch_bounds__(K1_THR, 1)
rowsum_bulk_kernel(const float* __restrict__ Mr, int I) {
    extern __shared__ char smem[];
    const int tid_g = blockIdx.x * K1_THR + threadIdx.x;

    // zero segment accumulators (completes before kernel 2 runs)
    for (int i = tid_g; i < NUM_SEG; i += K1_BLK * K1_THR) {
        g_segsum[i] = 0.0f;
        g_segcnt[i] = 0.0f;
    }

    const uint32_t sbase = smem_u32(smem);
    const uint32_t mbar0 = sbase + NSTAGE * TILE_BYTES;

    const int w    = threadIdx.x >> 5;   // 0..7
    const int lane = threadIdx.x & 31;

    if (threadIdx.x == 0) {
        #pragma unroll
        for (int s = 0; s < NSTAGE; s++) MBAR_INIT(mbar0 + s * 8, 1);
        asm volatile("fence.proxy.async.shared::cta;" ::: "memory");
    }
    __syncthreads();

    const int ntiles = (I + TILE_ROWS - 1) / TILE_ROWS;   // 1563

    // prefill up to NSTAGE tiles
    if (threadIdx.x == 0) {
        #pragma unroll
        for (int p = 0; p < NSTAGE; p++) {
            int t = blockIdx.x + p * K1_BLK;
            if (t < ntiles) {
                int rows = min(TILE_ROWS, I - t * TILE_ROWS);
                uint32_t bytes = (uint32_t)rows * 256u;
                MBAR_EXPECT_TX(mbar0 + p * 8, bytes);
                CP_ASYNC_BULK(sbase + p * TILE_BYTES,
                              (const void*)((const char*)Mr + (size_t)t * TILE_BYTES),
                              bytes, mbar0 + p * 8);
            }
        }
    }

    for (int k = 0; ; k++) {
        int t = blockIdx.x + k * K1_BLK;
        if (t >= ntiles) break;
        int s = k & (NSTAGE - 1);
        uint32_t parity = (k >> 2) & 1;

        mbar_wait(mbar0 + s * 8, parity);

        // reduce 64 rows: warp w -> rows w*8..w*8+7, f4 idx = w*128 + j*32 + lane
        const float4* sf4 = reinterpret_cast<const float4*>(smem + s * TILE_BYTES);
        float acc[4];
        #pragma unroll
        for (int j = 0; j < 4; j++) {
            float4 v = sf4[w * 128 + j * 32 + lane];
            acc[j] = (v.x + v.y) + (v.z + v.w);
        }
        #pragma unroll
        for (int o = 8; o; o >>= 1) {
            #pragma unroll
            for (int j = 0; j < 4; j++)
                acc[j] += __shfl_xor_sync(0xFFFFFFFFu, acc[j], o);
        }
        if ((lane & 15) == 0) {
            int rbase = t * TILE_ROWS + w * 8 + (lane >> 4);
            #pragma unroll
            for (int j = 0; j < 4; j++) {
                int r = rbase + j * 2;
                if (r < I) g_rowsum[r] = acc[j];
            }
        }

        __syncthreads();   // all threads done with stage s buffer

        if (threadIdx.x == 0) {
            int nt = blockIdx.x + (k + NSTAGE) * K1_BLK;
            if (nt < ntiles) {
                int rows = min(TILE_ROWS, I - nt * TILE_ROWS);
                uint32_t bytes = (uint32_t)rows * 256u;
                MBAR_EXPECT_TX(mbar0 + s * 8, bytes);
                CP_ASYNC_BULK(sbase + s * TILE_BYTES,
                              (const void*)((const char*)Mr + (size_t)nt * TILE_BYTES),
                              bytes, mbar0 + s * 8);
            }
        }
    }
}

// ---------------------------------------------------------------------------
// Kernel 2: segmented accumulation (blocks [0, SEGBLK)) +
//           per-sample dot/isum precompute (blocks [SEGBLK, SEGBLK+DOTBLK)).
// ---------------------------------------------------------------------------
#define CHUNK   16
#define SEGBLK  400        // 400*256*16 = 1,638,400 elements
#define DOTBLK  512        // 512*256/8  = 16,384 samples

__global__ void seg_dot_kernel(const int*   __restrict__ flat_items,
                               const int*   __restrict__ seg_ids,
                               const int*   __restrict__ item_idx,
                               const int*   __restrict__ user_idx,
                               const float* __restrict__ user_emb,
                               const float* __restrict__ item_emb,
                               int T, int Bn) {
    if (blockIdx.x < SEGBLK) {
        long base = (long)(blockIdx.x * blockDim.x + threadIdx.x) * CHUNK;
        if (base >= T) return;

        const int4* sg4 = reinterpret_cast<const int4*>(seg_ids + base);
        const int4* fi4 = reinterpret_cast<const int4*>(flat_items + base);

        int   cur   = -1;
        int   tgt   = -1;
        float acc_s = 0.0f;
        float acc_c = 0.0f;

        if (base + CHUNK <= T) {
            int4 sg[4], fi[4];
            #pragma unroll
            for (int v = 0; v < 4; v++) { sg[v] = sg4[v]; fi[v] = fi4[v]; }
            #pragma unroll
            for (int v = 0; v < 4; v++) {
                #pragma unroll
                for (int kk = 0; kk < 4; kk++) {
                    int seg = (kk == 0) ? sg[v].x : (kk == 1) ? sg[v].y : (kk == 2) ? sg[v].z : sg[v].w;
                    int it  = (kk == 0) ? fi[v].x : (kk == 1) ? fi[v].y : (kk == 2) ? fi[v].z : fi[v].w;
                    if (seg != cur) {
                        if (cur >= 0) {
                            atomicAdd(&g_segsum[cur], acc_s);
                            atomicAdd(&g_segcnt[cur], acc_c);
                        }
                        cur = seg; acc_s = 0.0f; acc_c = 0.0f;
                        tgt = item_idx[seg / 5];
                    }
                    if (it != tgt) {
                        acc_s += g_rowsum[it];
                        acc_c += 1.0f;
                    }
                }
            }
        } else {
            int n = (int)((long)T - base);
            for (int t = 0; t < n; t++) {
                int seg = seg_ids[base + t];
                int it  = flat_items[base + t];
                if (seg != cur) {
                    if (cur >= 0) {
                        atomicAdd(&g_segsum[cur], acc_s);
                        atomicAdd(&g_segcnt[cur], acc_c);
                    }
                    cur = seg; acc_s = 0.0f; acc_c = 0.0f;
                    tgt = item_idx[seg / 5];
                }
                if (it != tgt) {
                    acc_s += g_rowsum[it];
                    acc_c += 1.0f;
                }
            }
        }
        if (cur >= 0) {
            atomicAdd(&g_segsum[cur], acc_s);
            atomicAdd(&g_segcnt[cur], acc_c);
        }
    } else {
        // dot/isum precompute: 8 lanes per sample
        int t2     = (blockIdx.x - SEGBLK) * blockDim.x + threadIdx.x;
        int sample = t2 >> 3;
        int sub    = t2 & 7;
        if (sample >= Bn) return;

        int u = user_idx[sample];
        int i = item_idx[sample];

        const float4* ue = reinterpret_cast<const float4*>(user_emb + (long)u * 64);
        const float4* ie = reinterpret_cast<const float4*>(item_emb + (long)i * 64);

        float4 a0 = ue[sub];
        float4 a1 = ue[sub + 8];
        float4 b0 = ie[sub];
        float4 b1 = ie[sub + 8];

        float dot  = a0.x*b0.x + a0.y*b0.y + a0.z*b0.z + a0.w*b0.w
                   + a1.x*b1.x + a1.y*b1.y + a1.z*b1.z + a1.w*b1.w;
        float isum = b0.x + b0.y + b0.z + b0.w + b1.x + b1.y + b1.z + b1.w;

        #pragma unroll
        for (int o = 4; o; o >>= 1) {
            dot  += __shfl_xor_sync(0xFFFFFFFFu, dot,  o);
            isum += __shfl_xor_sync(0xFFFFFFFFu, isum, o);
        }
        if (sub == 0) {
            g_dot[sample]  = dot;
            g_isum[sample] = isum;
        }
    }
}

// ---------------------------------------------------------------------------
// Kernel 3: combine. One thread per sample.
// ---------------------------------------------------------------------------
__global__ void combine_kernel(const int*   __restrict__ user_idx,
                               const int*   __restrict__ item_idx,
                               const float* __restrict__ user_bias,
                               const float* __restrict__ item_bias,
                               const float* __restrict__ global_avg,
                               float* __restrict__ out,
                               int Bn) {
    int sample = blockIdx.x * blockDim.x + threadIdx.x;
    if (sample >= Bn) return;

    int u = user_idx[sample];
    int i = item_idx[sample];

    float uu = 0.0f;
    #pragma unroll
    for (int r = 0; r < 5; r++) {
        float c = g_segcnt[sample * 5 + r];
        float s = g_segsum[sample * 5 + r];
        if (c > 0.0f) uu += s * rsqrtf(fmaxf(c, 1.0f));
    }
    float rui = g_dot[sample] + uu * g_isum[sample]
              + user_bias[u] + item_bias[i] + global_avg[0];
    rui = fminf(fmaxf(rui, 1.0f), 5.0f);
    out[sample] = rui;
}

// ---------------------------------------------------------------------------
// Launch
// ---------------------------------------------------------------------------
extern "C" void kernel_launch(void* const* d_in, const int* in_sizes, int n_in,
                              void* d_out, int out_size) {
    const int*   user_idx   = (const int*)  d_in[0];
    const int*   item_idx   = (const int*)  d_in[1];
    const int*   flat_items = (const int*)  d_in[2];
    const int*   seg_ids    = (const int*)  d_in[3];
    const float* user_emb   = (const float*)d_in[4];
    const float* item_emb   = (const float*)d_in[5];
    const float* Mr         = (const float*)d_in[6];
    const float* user_bias  = (const float*)d_in[7];
    const float* item_bias  = (const float*)d_in[8];
    const float* global_avg = (const float*)d_in[9];
    float* out = (float*)d_out;

    const int Bn = in_sizes[0];            // 16384
    const int T  = in_sizes[2];            // 1,638,400
    const int I  = in_sizes[6] / 64;       // 100000

    static bool attr_set = false;
    if (!attr_set) {
        cudaFuncSetAttribute(rowsum_bulk_kernel,
                             cudaFuncAttributeMaxDynamicSharedMemorySize, K1_SMEM);
        attr_set = true;
    }

    // 1) zero accumulators + rowsum (bulk-copy pipeline)
    rowsum_bulk_kernel<<<K1_BLK, K1_THR, K1_SMEM>>>(Mr, I);

    // 2) segmented accumulation + dot/isum precompute
    seg_dot_kernel<<<SEGBLK + DOTBLK, 256>>>(flat_items, seg_ids, item_idx,
                                             user_idx, user_emb, item_emb, T, Bn);

    // 3) combine
    combine_kernel<<<(Bn + 255) / 256, 256>>>(user_idx, item_idx,
                                              user_bias, item_bias, global_avg,
                                              out, Bn);
}